// round 2
// baseline (speedup 1.0000x reference)
#include <cuda_runtime.h>
#include <cuda_bf16.h>
#include <math.h>

#define N_NODES 100000
#define N_EDGES 1600000
#define D 128
#define N_LAYERS 4
#define N_GRAPHS 512
#define LN_EPS 1e-5f

// ---------------- scratch (device globals; no allocation allowed) ----------------
__device__ __align__(16) float g_h[N_NODES * D];      // post-GEMM features
__device__ __align__(16) float g_cur[N_NODES * D];    // current layer features
__device__ int   g_rowptr[N_NODES + 1];
__device__ int   g_cnt[N_NODES];        // in-degree counts, then CSR cursor
__device__ int   g_esrc[N_EDGES];       // edge sources grouped by dst
__device__ __align__(16) float g_dis[N_NODES];        // deg^{-1/2} (with self loop)
__device__ __align__(16) float g_pool[N_GRAPHS * D];
__device__ __align__(16) float g_pcnt[N_GRAPHS];
__device__ int g_is64_ei;               // 1 if edge_index is int64, else int32
__device__ int g_is64_b;                // 1 if batch is int64, else int32

// ---------------- helpers ----------------
__device__ __forceinline__ int load_idx(const void* p, long long i, int is64) {
    return is64 ? (int)((const long long*)p)[i] : ((const int*)p)[i];
}

__device__ __forceinline__ float4 f4_fma(float4 a, float s, float4 acc) {
    acc.x = fmaf(a.x, s, acc.x); acc.y = fmaf(a.y, s, acc.y);
    acc.z = fmaf(a.z, s, acc.z); acc.w = fmaf(a.w, s, acc.w);
    return acc;
}

// ---------------- 0. dtype detector ----------------
// Sample odd int32 slots in [0, n). int64 data (nonneg, < 2^31, little-endian)
// has zero high-words at every odd slot; int32 data has random nonzero values.
__global__ void detect_kernel(const int* __restrict__ ei32, int n_e,
                              const int* __restrict__ b32,  int n_b) {
    __shared__ int cnt_e, cnt_b;
    if (threadIdx.x == 0) { cnt_e = 0; cnt_b = 0; }
    __syncthreads();
    for (int k = threadIdx.x; k < 256; k += blockDim.x) {
        long long pe = (long long)(2 * k + 1) * n_e / 512;
        pe |= 1; if (pe >= n_e) pe = (n_e - 1) | 1;
        if (pe < n_e && ei32[pe] != 0) atomicAdd(&cnt_e, 1);
        long long pb = (long long)(2 * k + 1) * n_b / 512;
        pb |= 1; if (pb >= n_b) pb = (n_b - 1) | 1;
        if (pb < n_b && b32[pb] != 0) atomicAdd(&cnt_b, 1);
    }
    __syncthreads();
    if (threadIdx.x == 0) {
        g_is64_ei = (cnt_e == 0) ? 1 : 0;
        g_is64_b  = (cnt_b == 0) ? 1 : 0;
    }
}

// ---------------- 1. zero counters ----------------
__global__ void zero_kernel() {
    int i = blockIdx.x * blockDim.x + threadIdx.x;
    if (i < N_NODES) g_cnt[i] = 0;
    if (i < N_GRAPHS * D) g_pool[i] = 0.f;
    if (i < N_GRAPHS) g_pcnt[i] = 0.f;
}

// ---------------- 2. in-degree histogram ----------------
__global__ void hist_kernel(const void* __restrict__ ei) {
    int i = blockIdx.x * blockDim.x + threadIdx.x;
    if (i >= N_EDGES) return;
    int is64 = g_is64_ei;
    int dst = load_idx(ei, (long long)N_EDGES + i, is64);
    atomicAdd(&g_cnt[dst], 1);
}

// ---------------- 3. exclusive scan (single block) ----------------
__global__ void scan_kernel() {
    __shared__ int ssum[1024];
    int t = threadIdx.x;
    const int C = (N_NODES + 1023) / 1024;
    int beg = t * C;
    int end = min(beg + C, N_NODES);
    int s = 0;
    for (int i = beg; i < end; ++i) s += g_cnt[i];
    ssum[t] = s;
    __syncthreads();
    for (int off = 1; off < 1024; off <<= 1) {
        int v = (t >= off) ? ssum[t - off] : 0;
        __syncthreads();
        ssum[t] += v;
        __syncthreads();
    }
    int run = (t == 0) ? 0 : ssum[t - 1];
    for (int i = beg; i < end; ++i) { g_rowptr[i] = run; run += g_cnt[i]; }
    if (t == 0) g_rowptr[N_NODES] = ssum[1023];
}

// ---------------- 4. deg_inv_sqrt + cursor init ----------------
__global__ void prep_kernel() {
    int v = blockIdx.x * blockDim.x + threadIdx.x;
    if (v >= N_NODES) return;
    g_dis[v] = rsqrtf((float)g_cnt[v] + 1.0f);
    g_cnt[v] = g_rowptr[v];   // becomes CSR fill cursor
}

// ---------------- 5. CSR fill ----------------
__global__ void fill_kernel(const void* __restrict__ ei) {
    int i = blockIdx.x * blockDim.x + threadIdx.x;
    if (i >= N_EDGES) return;
    int is64 = g_is64_ei;
    int src = load_idx(ei, i, is64);
    int dst = load_idx(ei, (long long)N_EDGES + i, is64);
    int pos = atomicAdd(&g_cnt[dst], 1);
    g_esrc[pos] = src;
}

// ---------------- 6. GEMM: out = in @ W   (M=N_NODES, K=D=128, N=D=128) ----------------
__global__ __launch_bounds__(256) void gemm_kernel(const float* __restrict__ in,
                                                   const float* __restrict__ W,
                                                   float* __restrict__ out,
                                                   int use_cur) {
    __shared__ float sX[128 * 32];
    __shared__ float sW[32 * 128];
    const float* A = use_cur ? g_cur : in;

    int tid = threadIdx.x;
    int tx = tid & 15;          // 16 col-groups of 8
    int ty = tid >> 4;          // 16 row-groups of 8
    int br = blockIdx.x * 128;

    float acc[8][8];
#pragma unroll
    for (int i = 0; i < 8; ++i)
#pragma unroll
        for (int j = 0; j < 8; ++j) acc[i][j] = 0.f;

    for (int kc = 0; kc < 4; ++kc) {
        int k0 = kc * 32;
#pragma unroll
        for (int it = 0; it < 4; ++it) {
            int idx = tid + it * 256;
            int row = idx >> 3, kq = idx & 7;
            float4 v = make_float4(0.f, 0.f, 0.f, 0.f);
            if (br + row < N_NODES)
                v = *(const float4*)&A[(size_t)(br + row) * D + k0 + kq * 4];
            *(float4*)&sX[row * 32 + kq * 4] = v;
        }
#pragma unroll
        for (int it = 0; it < 4; ++it) {
            int idx = tid + it * 256;
            int k = idx >> 5, q = idx & 31;
            *(float4*)&sW[k * 128 + q * 4] =
                *(const float4*)&W[(size_t)(k0 + k) * D + q * 4];
        }
        __syncthreads();

#pragma unroll
        for (int k = 0; k < 32; ++k) {
            float xv[8];
#pragma unroll
            for (int i = 0; i < 8; ++i) xv[i] = sX[(ty * 8 + i) * 32 + k];
            float4 w0 = *(float4*)&sW[k * 128 + tx * 8];
            float4 w1 = *(float4*)&sW[k * 128 + tx * 8 + 4];
#pragma unroll
            for (int i = 0; i < 8; ++i) {
                acc[i][0] = fmaf(xv[i], w0.x, acc[i][0]);
                acc[i][1] = fmaf(xv[i], w0.y, acc[i][1]);
                acc[i][2] = fmaf(xv[i], w0.z, acc[i][2]);
                acc[i][3] = fmaf(xv[i], w0.w, acc[i][3]);
                acc[i][4] = fmaf(xv[i], w1.x, acc[i][4]);
                acc[i][5] = fmaf(xv[i], w1.y, acc[i][5]);
                acc[i][6] = fmaf(xv[i], w1.z, acc[i][6]);
                acc[i][7] = fmaf(xv[i], w1.w, acc[i][7]);
            }
        }
        __syncthreads();
    }

#pragma unroll
    for (int i = 0; i < 8; ++i) {
        int row = br + ty * 8 + i;
        if (row < N_NODES) {
            float4 o0 = make_float4(acc[i][0], acc[i][1], acc[i][2], acc[i][3]);
            float4 o1 = make_float4(acc[i][4], acc[i][5], acc[i][6], acc[i][7]);
            *(float4*)&out[(size_t)row * D + tx * 8]     = o0;
            *(float4*)&out[(size_t)row * D + tx * 8 + 4] = o1;
        }
    }
}

// ---------------- 7. fused aggregation + bias + LN + residual/relu ----------------
// one warp per node; whole row (128 f32) = float4 per lane
// mode 0: relu only (layer 0); mode 1: +residual, relu; mode 2: +residual only
__global__ __launch_bounds__(256) void agg_kernel(const float* __restrict__ b,
                                                  const float* __restrict__ gamma,
                                                  const float* __restrict__ beta,
                                                  int mode) {
    int warp = (blockIdx.x * blockDim.x + threadIdx.x) >> 5;
    int lane = threadIdx.x & 31;
    if (warp >= N_NODES) return;
    int v = warp;

    const float4* h4 = (const float4*)g_h;
    float4* cur4 = (float4*)g_cur;

    int beg = g_rowptr[v];
    int end = g_rowptr[v + 1];

    float4 acc = make_float4(0.f, 0.f, 0.f, 0.f);
    int e = beg;
    for (; e + 4 <= end; e += 4) {
        int s0 = __ldg(&g_esrc[e]);
        int s1 = __ldg(&g_esrc[e + 1]);
        int s2 = __ldg(&g_esrc[e + 2]);
        int s3 = __ldg(&g_esrc[e + 3]);
        float w0 = __ldg(&g_dis[s0]);
        float w1 = __ldg(&g_dis[s1]);
        float w2 = __ldg(&g_dis[s2]);
        float w3 = __ldg(&g_dis[s3]);
        float4 t0 = h4[(size_t)s0 * 32 + lane];
        float4 t1 = h4[(size_t)s1 * 32 + lane];
        float4 t2 = h4[(size_t)s2 * 32 + lane];
        float4 t3 = h4[(size_t)s3 * 32 + lane];
        acc = f4_fma(t0, w0, acc);
        acc = f4_fma(t1, w1, acc);
        acc = f4_fma(t2, w2, acc);
        acc = f4_fma(t3, w3, acc);
    }
    for (; e < end; ++e) {
        int s = __ldg(&g_esrc[e]);
        float w = __ldg(&g_dis[s]);
        float4 t = h4[(size_t)s * 32 + lane];
        acc = f4_fma(t, w, acc);
    }

    float dv = g_dis[v];
    float4 self = h4[(size_t)v * 32 + lane];
    float dv2 = dv * dv;
    acc.x = fmaf(acc.x, dv, self.x * dv2);
    acc.y = fmaf(acc.y, dv, self.y * dv2);
    acc.z = fmaf(acc.z, dv, self.z * dv2);
    acc.w = fmaf(acc.w, dv, self.w * dv2);

    float4 bb = ((const float4*)b)[lane];
    acc.x += bb.x; acc.y += bb.y; acc.z += bb.z; acc.w += bb.w;

    // LayerNorm across 128 (warp reduce)
    float s1v = acc.x + acc.y + acc.z + acc.w;
    float s2v = acc.x * acc.x + acc.y * acc.y + acc.z * acc.z + acc.w * acc.w;
#pragma unroll
    for (int off = 16; off > 0; off >>= 1) {
        s1v += __shfl_xor_sync(0xffffffffu, s1v, off);
        s2v += __shfl_xor_sync(0xffffffffu, s2v, off);
    }
    float mu = s1v * (1.0f / 128.0f);
    float var = fmaf(s2v, 1.0f / 128.0f, -mu * mu);
    float inv = rsqrtf(var + LN_EPS);

    float4 g4 = ((const float4*)gamma)[lane];
    float4 be4 = ((const float4*)beta)[lane];
    float4 r;
    r.x = fmaf((acc.x - mu) * inv, g4.x, be4.x);
    r.y = fmaf((acc.y - mu) * inv, g4.y, be4.y);
    r.z = fmaf((acc.z - mu) * inv, g4.z, be4.z);
    r.w = fmaf((acc.w - mu) * inv, g4.w, be4.w);

    if (mode >= 1) {
        float4 res = cur4[(size_t)v * 32 + lane];
        r.x += res.x; r.y += res.y; r.z += res.z; r.w += res.w;
    }
    if (mode != 2) {
        r.x = fmaxf(r.x, 0.f); r.y = fmaxf(r.y, 0.f);
        r.z = fmaxf(r.z, 0.f); r.w = fmaxf(r.w, 0.f);
    }
    cur4[(size_t)v * 32 + lane] = r;
}

// ---------------- 8. pooling (mean over graphs) ----------------
__global__ __launch_bounds__(256) void pool_kernel(const void* __restrict__ batch) {
    int warp = (blockIdx.x * blockDim.x + threadIdx.x) >> 5;
    int lane = threadIdx.x & 31;
    if (warp >= N_NODES) return;
    int v = warp;
    int g = load_idx(batch, v, g_is64_b);
    float4 val = ((const float4*)g_cur)[(size_t)v * 32 + lane];
    float* dst = &g_pool[(size_t)g * D + lane * 4];
    asm volatile("red.global.add.v4.f32 [%0], {%1, %2, %3, %4};"
                 :: "l"(dst), "f"(val.x), "f"(val.y), "f"(val.z), "f"(val.w)
                 : "memory");
    if (lane == 0) atomicAdd(&g_pcnt[g], 1.0f);
}

// ---------------- 9. final linear ----------------
__global__ void final_kernel(const float* __restrict__ lin_w,
                             const float* __restrict__ lin_b,
                             float* __restrict__ out) {
    int g = blockIdx.x;
    int t = threadIdx.x;   // 128 threads
    float cnt = g_pcnt[g];
    float invc = 1.0f / fmaxf(cnt, 1.0f);
    float val = g_pool[(size_t)g * D + t] * invc * lin_w[t];
#pragma unroll
    for (int off = 16; off > 0; off >>= 1)
        val += __shfl_xor_sync(0xffffffffu, val, off);
    __shared__ float ws[4];
    if ((t & 31) == 0) ws[t >> 5] = val;
    __syncthreads();
    if (t == 0) out[g] = ws[0] + ws[1] + ws[2] + ws[3] + lin_b[0];
}

// ---------------- launch ----------------
extern "C" void kernel_launch(void* const* d_in, const int* in_sizes, int n_in,
                              void* d_out, int out_size) {
    // Defensive remap by element count (dict order among equal sizes).
    const void* x = 0; const void* ei = 0; const void* batch = 0;
    const void* Ws = 0; const void* lin_w = 0; const void* lin_b = 0;
    const void* small512[3] = {0, 0, 0};
    int n512 = 0;
    for (int i = 0; i < n_in; ++i) {
        switch (in_sizes[i]) {
            case N_NODES * D:      x = d_in[i]; break;
            case 2 * N_EDGES:      ei = d_in[i]; break;
            case N_NODES:          batch = d_in[i]; break;
            case N_LAYERS * D * D: Ws = d_in[i]; break;
            case D:                lin_w = d_in[i]; break;
            case 1:                lin_b = d_in[i]; break;
            case N_LAYERS * D:     if (n512 < 3) small512[n512++] = d_in[i]; break;
            default: break;
        }
    }
    const float* xf      = (const float*)x;
    const float* Wsf     = (const float*)Ws;
    const float* bsf     = (const float*)small512[0];
    const float* gammasf = (const float*)small512[1];
    const float* betasf  = (const float*)small512[2];
    const float* lin_wf  = (const float*)lin_w;
    const float* lin_bf  = (const float*)lin_b;
    float* out = (float*)d_out;

    float* h_ptr;   cudaGetSymbolAddress((void**)&h_ptr, g_h);

    detect_kernel<<<1, 256>>>((const int*)ei, 2 * N_EDGES, (const int*)batch, N_NODES);

    int zgrid = (N_NODES + 255) / 256;
    if ((N_GRAPHS * D + 255) / 256 > zgrid) zgrid = (N_GRAPHS * D + 255) / 256;
    zero_kernel<<<zgrid, 256>>>();
    hist_kernel<<<(N_EDGES + 255) / 256, 256>>>(ei);
    scan_kernel<<<1, 1024>>>();
    prep_kernel<<<(N_NODES + 255) / 256, 256>>>();
    fill_kernel<<<(N_EDGES + 255) / 256, 256>>>(ei);

    int ggrid = (N_NODES + 127) / 128;
    int agrid = (N_NODES * 32 + 255) / 256;
    for (int l = 0; l < N_LAYERS; ++l) {
        gemm_kernel<<<ggrid, 256>>>(xf, Wsf + (size_t)l * D * D, h_ptr, l > 0);
        int mode = (l == 0) ? 0 : (l == N_LAYERS - 1 ? 2 : 1);
        agg_kernel<<<agrid, 256>>>(bsf + (size_t)l * D, gammasf + (size_t)l * D,
                                   betasf + (size_t)l * D, mode);
    }

    pool_kernel<<<agrid, 256>>>(batch);
    final_kernel<<<N_GRAPHS, 128>>>(lin_wf, lin_bf, out);
}

// round 4
// speedup vs baseline: 1.8417x; 1.8417x over previous
#include <cuda_runtime.h>
#include <cuda_bf16.h>
#include <math.h>
#include <stdint.h>

#define N_NODES 100000
#define N_EDGES 1600000
#define D 128
#define N_LAYERS 4
#define N_GRAPHS 512
#define LN_EPS 1e-5f
#define NB_SCAN 391   // ceil(N_NODES/256)

// ---------------- scratch (device globals; no allocation allowed) ----------------
__device__ __align__(16) float g_h[N_NODES * D];      // post-GEMM features
__device__ __align__(16) float g_cur[N_NODES * D];    // current layer features
__device__ int   g_rowptr[N_NODES + 1];
__device__ int   g_cnt[N_NODES];        // in-degree counts, then CSR cursor
__device__ int   g_esrc[N_EDGES];       // edge sources grouped by dst
__device__ __align__(16) float g_dis[N_NODES];        // deg^{-1/2} (with self loop)
__device__ __align__(16) float g_pool[N_GRAPHS * D];
__device__ __align__(16) float g_pcnt[N_GRAPHS];
__device__ int g_bsum[NB_SCAN + 1];
__device__ int g_boff[NB_SCAN + 1];
__device__ int g_is64_ei;
__device__ int g_is64_b;

// ---------------- helpers ----------------
__device__ __forceinline__ int load_idx(const void* p, long long i, int is64) {
    return is64 ? (int)((const long long*)p)[i] : ((const int*)p)[i];
}

__device__ __forceinline__ float4 f4_fma(float4 a, float s, float4 acc) {
    acc.x = fmaf(a.x, s, acc.x); acc.y = fmaf(a.y, s, acc.y);
    acc.z = fmaf(a.z, s, acc.z); acc.w = fmaf(a.w, s, acc.w);
    return acc;
}

__device__ __forceinline__ uint32_t to_tf32(float f) {
    uint32_t u;
    asm("cvt.rna.tf32.f32 %0, %1;" : "=r"(u) : "f"(f));
    return u;
}

__device__ __forceinline__ void mma_tf32(float* c, const uint32_t* a, const uint32_t* b) {
    asm volatile(
        "mma.sync.aligned.m16n8k8.row.col.f32.tf32.tf32.f32 "
        "{%0,%1,%2,%3}, {%4,%5,%6,%7}, {%8,%9}, {%0,%1,%2,%3};"
        : "+f"(c[0]), "+f"(c[1]), "+f"(c[2]), "+f"(c[3])
        : "r"(a[0]), "r"(a[1]), "r"(a[2]), "r"(a[3]), "r"(b[0]), "r"(b[1]));
}

// ---------------- 0. dtype detector ----------------
// Sample odd int32 slots: int64 (nonneg < 2^31, LE) has zero high-words there.
__global__ void detect_kernel(const int* __restrict__ ei32, int n_e,
                              const int* __restrict__ b32,  int n_b) {
    __shared__ int cnt_e, cnt_b;
    if (threadIdx.x == 0) { cnt_e = 0; cnt_b = 0; }
    __syncthreads();
    for (int k = threadIdx.x; k < 256; k += blockDim.x) {
        long long pe = (long long)(2 * k + 1) * n_e / 512;
        pe |= 1; if (pe >= n_e) pe = (n_e - 1) | 1;
        if (pe < n_e && ei32[pe] != 0) atomicAdd(&cnt_e, 1);
        long long pb = (long long)(2 * k + 1) * n_b / 512;
        pb |= 1; if (pb >= n_b) pb = (n_b - 1) | 1;
        if (pb < n_b && b32[pb] != 0) atomicAdd(&cnt_b, 1);
    }
    __syncthreads();
    if (threadIdx.x == 0) {
        g_is64_ei = (cnt_e == 0) ? 1 : 0;
        g_is64_b  = (cnt_b == 0) ? 1 : 0;
    }
}

// ---------------- 1. zero counters ----------------
__global__ void zero_kernel() {
    int i = blockIdx.x * blockDim.x + threadIdx.x;
    if (i < N_NODES) g_cnt[i] = 0;
    if (i < N_GRAPHS * D) g_pool[i] = 0.f;
    if (i < N_GRAPHS) g_pcnt[i] = 0.f;
}

// ---------------- 2. in-degree histogram ----------------
__global__ void hist_kernel(const void* __restrict__ ei) {
    int i = blockIdx.x * blockDim.x + threadIdx.x;
    if (i >= N_EDGES) return;
    int dst = load_idx(ei, (long long)N_EDGES + i, g_is64_ei);
    atomicAdd(&g_cnt[dst], 1);
}

// ---------------- 3a. per-block reduce of g_cnt ----------------
__global__ __launch_bounds__(256) void scan_reduce_kernel() {
    int t = threadIdx.x, b = blockIdx.x;
    int i = b * 256 + t;
    int v = (i < N_NODES) ? g_cnt[i] : 0;
    int s = v;
#pragma unroll
    for (int off = 16; off > 0; off >>= 1) s += __shfl_xor_sync(0xffffffffu, s, off);
    __shared__ int ws[8];
    if ((t & 31) == 0) ws[t >> 5] = s;
    __syncthreads();
    if (t == 0) {
        int tot = 0;
#pragma unroll
        for (int w = 0; w < 8; ++w) tot += ws[w];
        g_bsum[b] = tot;
    }
}

// ---------------- 3b. scan block sums (single block, 512 thr) ----------------
__global__ __launch_bounds__(512) void scan_bsum_kernel() {
    __shared__ int s[512];
    int t = threadIdx.x;
    int v = (t < NB_SCAN) ? g_bsum[t] : 0;
    s[t] = v;
    __syncthreads();
#pragma unroll
    for (int off = 1; off < 512; off <<= 1) {
        int n = (t >= off) ? s[t - off] : 0;
        __syncthreads();
        s[t] += n;
        __syncthreads();
    }
    if (t < NB_SCAN) g_boff[t] = s[t] - v;   // exclusive
    if (t == 511) g_rowptr[N_NODES] = s[511];
}

// ---------------- 3c. per-block exclusive scan + global offset ----------------
__global__ __launch_bounds__(256) void scan_block_kernel() {
    int t = threadIdx.x, b = blockIdx.x;
    int lane = t & 31, wid = t >> 5;
    int i = b * 256 + t;
    int v = (i < N_NODES) ? g_cnt[i] : 0;
    int incl = v;
#pragma unroll
    for (int off = 1; off < 32; off <<= 1) {
        int n = __shfl_up_sync(0xffffffffu, incl, off);
        if (lane >= off) incl += n;
    }
    __shared__ int wsum[8], woff[8];
    if (lane == 31) wsum[wid] = incl;
    __syncthreads();
    if (wid == 0 && lane < 8) {
        int wv = wsum[lane];
        int wi = wv;
#pragma unroll
        for (int off = 1; off < 8; off <<= 1) {
            int n = __shfl_up_sync(0xffu, wi, off);
            if (lane >= off) wi += n;
        }
        woff[lane] = wi - wv;
    }
    __syncthreads();
    if (i < N_NODES) g_rowptr[i] = g_boff[b] + woff[wid] + (incl - v);
}

// ---------------- 4. deg_inv_sqrt + cursor init ----------------
__global__ void prep_kernel() {
    int v = blockIdx.x * blockDim.x + threadIdx.x;
    if (v >= N_NODES) return;
    g_dis[v] = rsqrtf((float)g_cnt[v] + 1.0f);
    g_cnt[v] = g_rowptr[v];   // becomes CSR fill cursor
}

// ---------------- 5. CSR fill ----------------
__global__ void fill_kernel(const void* __restrict__ ei) {
    int i = blockIdx.x * blockDim.x + threadIdx.x;
    if (i >= N_EDGES) return;
    int is64 = g_is64_ei;
    int src = load_idx(ei, i, is64);
    int dst = load_idx(ei, (long long)N_EDGES + i, is64);
    int pos = atomicAdd(&g_cnt[dst], 1);
    g_esrc[pos] = src;
}

// ---------------- 6. TF32 tensor-core GEMM: out = A @ W  (M=N_NODES, K=N=128) ----
// 128x128 block tile, 8 warps of 32x64, m16n8k8 TF32 mma, fp32 accumulate.
__global__ __launch_bounds__(256) void gemm_tc_kernel(const float* __restrict__ A,
                                                      const float* __restrict__ W,
                                                      float* __restrict__ out) {
    __shared__ uint32_t sX[128 * 36];   // stride 36 -> conflict-free A frags
    __shared__ uint32_t sW[32 * 132];   // stride 132 -> <=2-way on B frags
    int tid = threadIdx.x;
    int lane = tid & 31, wid = tid >> 5;
    int warp_m = wid >> 1, warp_n = wid & 1;
    int tg = lane >> 2, tc = lane & 3;
    int br = blockIdx.x * 128;

    float acc[2][8][4];
#pragma unroll
    for (int mt = 0; mt < 2; ++mt)
#pragma unroll
        for (int nt = 0; nt < 8; ++nt)
#pragma unroll
            for (int q = 0; q < 4; ++q) acc[mt][nt][q] = 0.f;

    for (int kc = 0; kc < 4; ++kc) {
        int k0 = kc * 32;
#pragma unroll
        for (int it = 0; it < 4; ++it) {
            int idx = tid + it * 256;
            int row = idx >> 3, kq = idx & 7;
            float4 v = make_float4(0.f, 0.f, 0.f, 0.f);
            if (br + row < N_NODES)
                v = *(const float4*)&A[(size_t)(br + row) * D + k0 + kq * 4];
            uint4 u = make_uint4(to_tf32(v.x), to_tf32(v.y), to_tf32(v.z), to_tf32(v.w));
            *(uint4*)&sX[row * 36 + kq * 4] = u;
        }
#pragma unroll
        for (int it = 0; it < 4; ++it) {
            int idx = tid + it * 256;
            int k = idx >> 5, q = idx & 31;
            float4 v = *(const float4*)&W[(size_t)(k0 + k) * D + q * 4];
            uint4 u = make_uint4(to_tf32(v.x), to_tf32(v.y), to_tf32(v.z), to_tf32(v.w));
            *(uint4*)&sW[k * 132 + q * 4] = u;
        }
        __syncthreads();

#pragma unroll
        for (int kk = 0; kk < 4; ++kk) {
            uint32_t a[2][4], b[8][2];
#pragma unroll
            for (int mt = 0; mt < 2; ++mt) {
                int r0 = warp_m * 32 + mt * 16 + tg;
                a[mt][0] = sX[r0 * 36 + kk * 8 + tc];
                a[mt][1] = sX[(r0 + 8) * 36 + kk * 8 + tc];
                a[mt][2] = sX[r0 * 36 + kk * 8 + tc + 4];
                a[mt][3] = sX[(r0 + 8) * 36 + kk * 8 + tc + 4];
            }
#pragma unroll
            for (int nt = 0; nt < 8; ++nt) {
                int n0 = warp_n * 64 + nt * 8 + tg;
                b[nt][0] = sW[(kk * 8 + tc) * 132 + n0];
                b[nt][1] = sW[(kk * 8 + 4 + tc) * 132 + n0];
            }
#pragma unroll
            for (int mt = 0; mt < 2; ++mt)
#pragma unroll
                for (int nt = 0; nt < 8; ++nt)
                    mma_tf32(acc[mt][nt], a[mt], b[nt]);
        }
        __syncthreads();
    }

#pragma unroll
    for (int mt = 0; mt < 2; ++mt) {
        int r0 = br + warp_m * 32 + mt * 16 + tg;
#pragma unroll
        for (int nt = 0; nt < 8; ++nt) {
            int c0 = warp_n * 64 + nt * 8 + 2 * tc;
            if (r0 < N_NODES)
                *(float2*)&out[(size_t)r0 * D + c0] =
                    make_float2(acc[mt][nt][0], acc[mt][nt][1]);
            if (r0 + 8 < N_NODES)
                *(float2*)&out[(size_t)(r0 + 8) * D + c0] =
                    make_float2(acc[mt][nt][2], acc[mt][nt][3]);
        }
    }
}

// ---------------- 7. fused aggregation + bias + LN + residual/relu (+pool) -------
// one warp per node; whole row (128 f32) = float4 per lane
// mode 0: relu (layer 0); mode 1: +residual, relu; mode 2: +residual, fused pool
__global__ __launch_bounds__(256) void agg_kernel(const float* __restrict__ b,
                                                  const float* __restrict__ gamma,
                                                  const float* __restrict__ beta,
                                                  const void* __restrict__ batch,
                                                  int mode) {
    int warp = (blockIdx.x * blockDim.x + threadIdx.x) >> 5;
    int lane = threadIdx.x & 31;
    if (warp >= N_NODES) return;
    int v = warp;

    const float4* h4 = (const float4*)g_h;
    float4* cur4 = (float4*)g_cur;

    int beg = g_rowptr[v];
    int end = g_rowptr[v + 1];

    float4 acc = make_float4(0.f, 0.f, 0.f, 0.f);
    int e = beg;
    for (; e + 4 <= end; e += 4) {
        int s0 = __ldg(&g_esrc[e]);
        int s1 = __ldg(&g_esrc[e + 1]);
        int s2 = __ldg(&g_esrc[e + 2]);
        int s3 = __ldg(&g_esrc[e + 3]);
        float w0 = __ldg(&g_dis[s0]);
        float w1 = __ldg(&g_dis[s1]);
        float w2 = __ldg(&g_dis[s2]);
        float w3 = __ldg(&g_dis[s3]);
        float4 t0 = h4[(size_t)s0 * 32 + lane];
        float4 t1 = h4[(size_t)s1 * 32 + lane];
        float4 t2 = h4[(size_t)s2 * 32 + lane];
        float4 t3 = h4[(size_t)s3 * 32 + lane];
        acc = f4_fma(t0, w0, acc);
        acc = f4_fma(t1, w1, acc);
        acc = f4_fma(t2, w2, acc);
        acc = f4_fma(t3, w3, acc);
    }
    for (; e < end; ++e) {
        int s = __ldg(&g_esrc[e]);
        float w = __ldg(&g_dis[s]);
        float4 t = h4[(size_t)s * 32 + lane];
        acc = f4_fma(t, w, acc);
    }

    float dv = g_dis[v];
    float4 self = h4[(size_t)v * 32 + lane];
    float dv2 = dv * dv;
    acc.x = fmaf(acc.x, dv, self.x * dv2);
    acc.y = fmaf(acc.y, dv, self.y * dv2);
    acc.z = fmaf(acc.z, dv, self.z * dv2);
    acc.w = fmaf(acc.w, dv, self.w * dv2);

    float4 bb = ((const float4*)b)[lane];
    acc.x += bb.x; acc.y += bb.y; acc.z += bb.z; acc.w += bb.w;

    // LayerNorm across 128 (warp reduce)
    float s1v = acc.x + acc.y + acc.z + acc.w;
    float s2v = acc.x * acc.x + acc.y * acc.y + acc.z * acc.z + acc.w * acc.w;
#pragma unroll
    for (int off = 16; off > 0; off >>= 1) {
        s1v += __shfl_xor_sync(0xffffffffu, s1v, off);
        s2v += __shfl_xor_sync(0xffffffffu, s2v, off);
    }
    float mu = s1v * (1.0f / 128.0f);
    float var = fmaf(s2v, 1.0f / 128.0f, -mu * mu);
    float inv = rsqrtf(var + LN_EPS);

    float4 g4 = ((const float4*)gamma)[lane];
    float4 be4 = ((const float4*)beta)[lane];
    float4 r;
    r.x = fmaf((acc.x - mu) * inv, g4.x, be4.x);
    r.y = fmaf((acc.y - mu) * inv, g4.y, be4.y);
    r.z = fmaf((acc.z - mu) * inv, g4.z, be4.z);
    r.w = fmaf((acc.w - mu) * inv, g4.w, be4.w);

    if (mode >= 1) {
        float4 res = cur4[(size_t)v * 32 + lane];
        r.x += res.x; r.y += res.y; r.z += res.z; r.w += res.w;
    }
    if (mode != 2) {
        r.x = fmaxf(r.x, 0.f); r.y = fmaxf(r.y, 0.f);
        r.z = fmaxf(r.z, 0.f); r.w = fmaxf(r.w, 0.f);
        cur4[(size_t)v * 32 + lane] = r;
    } else {
        // final layer: skip writeback, pool directly
        int g = load_idx(batch, v, g_is64_b);
        float* dst = &g_pool[(size_t)g * D + lane * 4];
        asm volatile("red.global.add.v4.f32 [%0], {%1, %2, %3, %4};"
                     :: "l"(dst), "f"(r.x), "f"(r.y), "f"(r.z), "f"(r.w)
                     : "memory");
        if (lane == 0) atomicAdd(&g_pcnt[g], 1.0f);
    }
}

// ---------------- 9. final linear ----------------
__global__ void final_kernel(const float* __restrict__ lin_w,
                             const float* __restrict__ lin_b,
                             float* __restrict__ out) {
    int g = blockIdx.x;
    int t = threadIdx.x;   // 128 threads
    float cnt = g_pcnt[g];
    float invc = 1.0f / fmaxf(cnt, 1.0f);
    float val = g_pool[(size_t)g * D + t] * invc * lin_w[t];
#pragma unroll
    for (int off = 16; off > 0; off >>= 1)
        val += __shfl_xor_sync(0xffffffffu, val, off);
    __shared__ float ws[4];
    if ((t & 31) == 0) ws[t >> 5] = val;
    __syncthreads();
    if (t == 0) out[g] = ws[0] + ws[1] + ws[2] + ws[3] + lin_b[0];
}

// ---------------- launch ----------------
extern "C" void kernel_launch(void* const* d_in, const int* in_sizes, int n_in,
                              void* d_out, int out_size) {
    const void* x = 0; const void* ei = 0; const void* batch = 0;
    const void* Ws = 0; const void* lin_w = 0; const void* lin_b = 0;
    const void* small512[3] = {0, 0, 0};
    int n512 = 0;
    for (int i = 0; i < n_in; ++i) {
        switch (in_sizes[i]) {
            case N_NODES * D:      x = d_in[i]; break;
            case 2 * N_EDGES:      ei = d_in[i]; break;
            case N_NODES:          batch = d_in[i]; break;
            case N_LAYERS * D * D: Ws = d_in[i]; break;
            case D:                lin_w = d_in[i]; break;
            case 1:                lin_b = d_in[i]; break;
            case N_LAYERS * D:     if (n512 < 3) small512[n512++] = d_in[i]; break;
            default: break;
        }
    }
    const float* xf      = (const float*)x;
    const float* Wsf     = (const float*)Ws;
    const float* bsf     = (const float*)small512[0];
    const float* gammasf = (const float*)small512[1];
    const float* betasf  = (const float*)small512[2];
    const float* lin_wf  = (const float*)lin_w;
    const float* lin_bf  = (const float*)lin_b;
    float* out = (float*)d_out;

    float* h_ptr;   cudaGetSymbolAddress((void**)&h_ptr, g_h);
    float* cur_ptr; cudaGetSymbolAddress((void**)&cur_ptr, g_cur);

    detect_kernel<<<1, 256>>>((const int*)ei, 2 * N_EDGES, (const int*)batch, N_NODES);

    int zgrid = (N_NODES + 255) / 256;
    if ((N_GRAPHS * D + 255) / 256 > zgrid) zgrid = (N_GRAPHS * D + 255) / 256;
    zero_kernel<<<zgrid, 256>>>();
    hist_kernel<<<(N_EDGES + 255) / 256, 256>>>(ei);
    scan_reduce_kernel<<<NB_SCAN, 256>>>();
    scan_bsum_kernel<<<1, 512>>>();
    scan_block_kernel<<<NB_SCAN, 256>>>();
    prep_kernel<<<(N_NODES + 255) / 256, 256>>>();
    fill_kernel<<<(N_EDGES + 255) / 256, 256>>>(ei);

    int ggrid = (N_NODES + 127) / 128;
    int agrid = (N_NODES * 32 + 255) / 256;
    for (int l = 0; l < N_LAYERS; ++l) {
        const float* A = (l == 0) ? xf : cur_ptr;
        gemm_tc_kernel<<<ggrid, 256>>>(A, Wsf + (size_t)l * D * D, h_ptr);
        int mode = (l == 0) ? 0 : (l == N_LAYERS - 1 ? 2 : 1);
        agg_kernel<<<agrid, 256>>>(bsf + (size_t)l * D, gammasf + (size_t)l * D,
                                   betasf + (size_t)l * D, batch, mode);
    }

    final_kernel<<<N_GRAPHS, 128>>>(lin_wf, lin_bf, out);
}